// round 9
// baseline (speedup 1.0000x reference)
#include <cuda_runtime.h>
#include <cstdint>

#define BATCH 4
#define SEQ   2048
#define INF   4096
#define OUTF  4096
#define RANK  16
// SCALING = 16/16 = 1.0f (elided)

// ---- phase-1 (warp MMA) ----
#define P1_T      256
#define P1_ROWS   128                 // rows per CTA (8 warps x m16)
#define P1_SPLIT  4
#define KS_TOT    (INF / 16)          // 256 k-steps total
#define KS_SPLIT  (KS_TOT / P1_SPLIT) // 64 per split

// ---- phase-2 (SIMT, proven) ----
#define T2     256
#define ROWS2  128
#define OPT    4
#define OTILE  (T2 * OPT)             // 1024
#define BXP    9

typedef unsigned long long ull;

// scratch
__device__ float    g_bx[P1_SPLIT * BATCH * SEQ * RANK];        // 2 MB partials
__device__ uint32_t g_Bc[8 * 2 * KS_TOT * 2 * 2 * 32];          // 2 MB frag-packed B

// ---- helpers --------------------------------------------------------------
__device__ __forceinline__ void fma2(ull& d, ull a, ull b) {
    asm("fma.rn.f32x2 %0, %1, %2, %0;" : "+l"(d) : "l"(a), "l"(b));
}
__device__ __forceinline__ ull pack2(float lo, float hi) {
    ull d; asm("mov.b64 %0, {%1, %2};" : "=l"(d) : "f"(lo), "f"(hi)); return d;
}
__device__ __forceinline__ void unpack2(float& lo, float& hi, ull d) {
    asm("mov.b64 {%0, %1}, %2;" : "=f"(lo), "=f"(hi) : "l"(d));
}
// bf16x2 pack: low half = hi-bits of f0, high half = hi-bits of f1 (truncation)
__device__ __forceinline__ uint32_t bfhi2(float f0, float f1) {
    return __byte_perm(__float_as_uint(f0), __float_as_uint(f1), 0x7632);
}
__device__ __forceinline__ uint32_t bflo2(float f0, float f1) {
    const float l0 = f0 - __uint_as_float(__float_as_uint(f0) & 0xFFFF0000u);
    const float l1 = f1 - __uint_as_float(__float_as_uint(f1) & 0xFFFF0000u);
    return __byte_perm(__float_as_uint(l0), __float_as_uint(l1), 0x7632);
}
__device__ __forceinline__ void mma16816(float* d,
    uint32_t a0, uint32_t a1, uint32_t a2, uint32_t a3,
    uint32_t b0, uint32_t b1)
{
    asm volatile(
        "mma.sync.aligned.m16n8k16.row.col.f32.bf16.bf16.f32 "
        "{%0,%1,%2,%3}, {%4,%5,%6,%7}, {%8,%9}, {%0,%1,%2,%3};"
        : "+f"(d[0]), "+f"(d[1]), "+f"(d[2]), "+f"(d[3])
        : "r"(a0), "r"(a1), "r"(a2), "r"(a3), "r"(b0), "r"(b1));
}

// ---------------------------------------------------------------------------
// K0: pack B[8][16][4096] fp32 into fragment-exact bf16 pairs.
// Layout: g_Bc[((((a*2+h)*KS_TOT + ks)*2 + j)*2 + t)*32 + lane]
//   = bf16pair of B[a][t*8 + lane>>2][ks*16 + j*8 + (lane&3)*2 + {0,1}], term h.
// ---------------------------------------------------------------------------
__global__ void lora_conv_b(const float* __restrict__ Bw)
{
    const int idx = blockIdx.x * blockDim.x + threadIdx.x;
    if (idx >= 8 * 2 * KS_TOT * 2 * 2 * 32) return;
    const int lane = idx & 31;
    const int t    = (idx >> 5) & 1;
    const int j    = (idx >> 6) & 1;
    const int ks   = (idx >> 7) & (KS_TOT - 1);
    const int h    = (idx >> 15) & 1;
    const int a    = idx >> 16;
    const int r    = t * 8 + (lane >> 2);
    const int k    = ks * 16 + j * 8 + (lane & 3) * 2;
    const float* p = Bw + ((size_t)a * RANK + r) * INF + k;
    const float f0 = p[0], f1 = p[1];
    g_Bc[idx] = h ? bflo2(f0, f1) : bfhi2(f0, f1);
}

// ---------------------------------------------------------------------------
// K1: phase-1 on tensor cores (split-bf16, 3 terms).
// Warp = one m16 row tile; K split 4 ways; no smem, no barriers in k-loop.
// ---------------------------------------------------------------------------
__global__ __launch_bounds__(P1_T) void lora_p1_mma(
    const float* __restrict__ x,
    const int*   __restrict__ ids)
{
    const int tid  = threadIdx.x;
    const int wid  = tid >> 5;
    const int lane = tid & 31;
    const int tig  = lane & 3;
    const int b    = blockIdx.y;
    const int sp   = blockIdx.z;
    const int aid  = ids[b];

    const int row0 = blockIdx.x * P1_ROWS + wid * 16 + (lane >> 2);
    const float* xr0 = x + ((size_t)b * SEQ + row0) * INF;
    const float* xr8 = xr0 + 8 * INF;

    // (a, h) bases into packed B; per-kstep stride = 2*2*32 = 128 words
    const uint32_t* Bhi = g_Bc + (size_t)(aid * 2 + 0) * (KS_TOT * 128);
    const uint32_t* Blo = g_Bc + (size_t)(aid * 2 + 1) * (KS_TOT * 128);

    float acc0[4] = {0.f, 0.f, 0.f, 0.f};   // ranks 0-7
    float acc1[4] = {0.f, 0.f, 0.f, 0.f};   // ranks 8-15

    const int ks0 = sp * KS_SPLIT;
#pragma unroll 2
    for (int ks = ks0; ks < ks0 + KS_SPLIT; ++ks) {
        const int k = ks * 16 + tig * 2;
        const float2 f0 = *(const float2*)(xr0 + k);        // (row g,   k)
        const float2 f1 = *(const float2*)(xr8 + k);        // (row g+8, k)
        const float2 f2 = *(const float2*)(xr0 + k + 8);    // (row g,   k+8)
        const float2 f3 = *(const float2*)(xr8 + k + 8);    // (row g+8, k+8)

        const uint32_t ah0 = bfhi2(f0.x, f0.y), ah1 = bfhi2(f1.x, f1.y);
        const uint32_t ah2 = bfhi2(f2.x, f2.y), ah3 = bfhi2(f3.x, f3.y);
        const uint32_t al0 = bflo2(f0.x, f0.y), al1 = bflo2(f1.x, f1.y);
        const uint32_t al2 = bflo2(f2.x, f2.y), al3 = bflo2(f3.x, f3.y);

        const uint32_t* bp = Bhi + ks * 128 + lane;
        const uint32_t* lp = Blo + ks * 128 + lane;
        const uint32_t bh00 = bp[0],  bh01 = bp[64];   // t=0: j=0, j=1
        const uint32_t bh10 = bp[32], bh11 = bp[96];   // t=1
        const uint32_t bl00 = lp[0],  bl01 = lp[64];
        const uint32_t bl10 = lp[32], bl11 = lp[96];

        mma16816(acc0, ah0, ah1, ah2, ah3, bh00, bh01);   // hi*hi
        mma16816(acc0, al0, al1, al2, al3, bh00, bh01);   // lo*hi
        mma16816(acc0, ah0, ah1, ah2, ah3, bl00, bl01);   // hi*lo
        mma16816(acc1, ah0, ah1, ah2, ah3, bh10, bh11);
        mma16816(acc1, al0, al1, al2, al3, bh10, bh11);
        mma16816(acc1, ah0, ah1, ah2, ah3, bl10, bl11);
    }

    // store partials: c0/c1 -> (row g, cols 2*tig+{0,1}); c2/c3 -> row g+8
    float* d0 = g_bx + ((size_t)(sp * BATCH + b) * SEQ + row0) * RANK;
    float* d8 = d0 + 8 * RANK;
    *(float2*)(d0 + tig * 2)     = make_float2(acc0[0], acc0[1]);
    *(float2*)(d8 + tig * 2)     = make_float2(acc0[2], acc0[3]);
    *(float2*)(d0 + 8 + tig * 2) = make_float2(acc1[0], acc1[1]);
    *(float2*)(d8 + 8 + tig * 2) = make_float2(acc1[2], acc1[3]);
}

// ---------------------------------------------------------------------------
// Phase 2 (fused split-reduce): out[b][n][o] = sum_r Bx[b][n][r]*A[aid][o][r]
// Thread owns 4 consecutive o; A pairs (32 ull) in regs; Bx dup'd in smem.
// ---------------------------------------------------------------------------
__global__ __launch_bounds__(T2, 2) void lora_phase2(
    const float* __restrict__ Aw,
    const int*   __restrict__ ids,
    float*       __restrict__ out)
{
    __shared__ ulonglong2 bxd[ROWS2 * BXP];      // 18.4 KB

    const int tid = threadIdx.x;
    const int o   = blockIdx.x * OTILE + tid * OPT;
    const int n0  = blockIdx.y * ROWS2;
    const int b   = blockIdx.z;
    const int aid = ids[b];

    // A pairs: ap01[r] = (A[o][r], A[o+1][r]); ap23[r] = (A[o+2][r], A[o+3][r])
    ull ap01[16], ap23[16];
    {
        const float* Ab = Aw + ((size_t)aid * OUTF + o) * RANK;
        float a0[16], a1[16], a2[16], a3[16];
#pragma unroll
        for (int j = 0; j < 4; ++j) {
            float4 v;
            v = *(const float4*)(Ab + 0 * RANK + 4 * j);
            a0[4*j]=v.x; a0[4*j+1]=v.y; a0[4*j+2]=v.z; a0[4*j+3]=v.w;
            v = *(const float4*)(Ab + 1 * RANK + 4 * j);
            a1[4*j]=v.x; a1[4*j+1]=v.y; a1[4*j+2]=v.z; a1[4*j+3]=v.w;
            v = *(const float4*)(Ab + 2 * RANK + 4 * j);
            a2[4*j]=v.x; a2[4*j+1]=v.y; a2[4*j+2]=v.z; a2[4*j+3]=v.w;
            v = *(const float4*)(Ab + 3 * RANK + 4 * j);
            a3[4*j]=v.x; a3[4*j+1]=v.y; a3[4*j+2]=v.z; a3[4*j+3]=v.w;
        }
#pragma unroll
        for (int r = 0; r < 16; ++r) {
            ap01[r] = pack2(a0[r], a1[r]);
            ap23[r] = pack2(a2[r], a3[r]);
        }
    }

    // fused reduce (4 split partials) + duplicate staging: 2 threads per row
    {
        const int row  = tid >> 1;
        const int half = tid & 1;
        const float* base = g_bx + ((size_t)b * SEQ + n0 + row) * RANK + half * 8;
        float4 u = make_float4(0.f, 0.f, 0.f, 0.f);
        float4 v = make_float4(0.f, 0.f, 0.f, 0.f);
#pragma unroll
        for (int s = 0; s < P1_SPLIT; ++s) {
            const float4* p =
                (const float4*)(base + (size_t)s * BATCH * SEQ * RANK);
            const float4 pa = p[0], pb = p[1];
            u.x += pa.x; u.y += pa.y; u.z += pa.z; u.w += pa.w;
            v.x += pb.x; v.y += pb.y; v.z += pb.z; v.w += pb.w;
        }
        const float w[8] = {u.x, u.y, u.z, u.w, v.x, v.y, v.z, v.w};
#pragma unroll
        for (int i = 0; i < 4; ++i) {
            ulonglong2 e;
            e.x = pack2(w[2*i],   w[2*i]);
            e.y = pack2(w[2*i+1], w[2*i+1]);
            bxd[row * BXP + half * 4 + i] = e;
        }
    }
    __syncthreads();

    float4* outp = (float4*)(out + ((size_t)b * SEQ + n0) * OUTF + o);

#pragma unroll 1
    for (int n = 0; n < ROWS2; n += 2) {
        const ulonglong2* r0 = bxd + n * BXP;
        const ulonglong2* r1 = r0 + BXP;
        ull A0=0, A1=0, A2=0, A3=0, B0=0, B1=0, B2=0, B3=0;
#pragma unroll
        for (int p = 0; p < 4; ++p) {            // ranks 0-7
            const ulonglong2 ba = r0[p], bb = r1[p];
            fma2(A0, ap01[2*p], ba.x); fma2(A0, ap01[2*p+1], ba.y);
            fma2(A1, ap23[2*p], ba.x); fma2(A1, ap23[2*p+1], ba.y);
            fma2(B0, ap01[2*p], bb.x); fma2(B0, ap01[2*p+1], bb.y);
            fma2(B1, ap23[2*p], bb.x); fma2(B1, ap23[2*p+1], bb.y);
        }
#pragma unroll
        for (int p = 4; p < 8; ++p) {            // ranks 8-15
            const ulonglong2 ba = r0[p], bb = r1[p];
            fma2(A2, ap01[2*p], ba.x); fma2(A2, ap01[2*p+1], ba.y);
            fma2(A3, ap23[2*p], ba.x); fma2(A3, ap23[2*p+1], ba.y);
            fma2(B2, ap01[2*p], bb.x); fma2(B2, ap01[2*p+1], bb.y);
            fma2(B3, ap23[2*p], bb.x); fma2(B3, ap23[2*p+1], bb.y);
        }
        float4 res0, res1;
        float l0, h0, l1, h1;
        unpack2(l0, h0, A0); unpack2(l1, h1, A2); res0.x = l0+l1; res0.y = h0+h1;
        unpack2(l0, h0, A1); unpack2(l1, h1, A3); res0.z = l0+l1; res0.w = h0+h1;
        unpack2(l0, h0, B0); unpack2(l1, h1, B2); res1.x = l0+l1; res1.y = h0+h1;
        unpack2(l0, h0, B1); unpack2(l1, h1, B3); res1.z = l0+l1; res1.w = h0+h1;
        outp[(size_t)n       * (OUTF / 4)] = res0;
        outp[(size_t)(n + 1) * (OUTF / 4)] = res1;
    }
}

// ---------------------------------------------------------------------------
extern "C" void kernel_launch(void* const* d_in, const int* in_sizes, int n_in,
                              void* d_out, int out_size)
{
    const float* x   = (const float*)d_in[0];   // [4,2048,4096]
    const float* Aw  = (const float*)d_in[1];   // [8,4096,16]
    const float* Bw  = (const float*)d_in[2];   // [8,16,4096]
    const int*   ids = (const int*)  d_in[3];   // [4]
    float*       out = (float*)d_out;           // [4,2048,4096]

    // K0: pack B into fragment layout (bf16 hi/lo)
    lora_conv_b<<<(8 * 2 * KS_TOT * 2 * 2 * 32) / 256, 256>>>(Bw);

    // K1: phase-1 tensor MMA
    dim3 g1(SEQ / P1_ROWS, BATCH, P1_SPLIT);    // (16,4,4) = 256 CTAs
    lora_p1_mma<<<g1, P1_T>>>(x, ids);

    // K2: phase-2 SIMT
    dim3 g2(OUTF / OTILE, SEQ / ROWS2, BATCH);  // (4,16,4) = 256 CTAs
    lora_phase2<<<g2, T2>>>(Aw, ids, out);
}